// round 6
// baseline (speedup 1.0000x reference)
#include <cuda_runtime.h>
#include <cuda_fp16.h>
#include <cstdint>
#include <cstddef>

// ----------------------------------------------------------------------------
// ThickConv2d as one fp16 mma.sync GEMM:
//   A (im2col of x, fp16) [8192 x 1152] @ W1^T (fp16) [1152 x 8192]
//   fp32 accum -> epilogue: +b1, leaky(0.1), 64-wide w2 contraction, +b2
// CTA tile 128x256, warp tile 64x64 (8 warps 2x4), 1 sync/chunk,
// shuffle-only epilogue. Cuts smem traffic per MMA ~1.5x vs 422us baseline.
// ----------------------------------------------------------------------------

#define P_TOT   8192
#define K_TOT   1152
#define N_TOT   8192
#define BM      128
#define BN      256           // = 4 output channels x 64 mid
#define BK      64            // halves per chunk (128B rows)
#define NCH     18            // 1152/64
#define STAGES  3
#define STAGE_BYTES ((BM + BN) * 128)            // 49152
#define CONST_OFF   (STAGES * STAGE_BYTES)       // 147456
#define SMEM_BYTES  (CONST_OFF + 1024 + 1024 + 16)

__device__ __half g_A[(size_t)P_TOT * K_TOT];
__device__ __half g_B[(size_t)N_TOT * K_TOT];

__device__ __forceinline__ uint32_t smem_u32(const void* p) {
    uint32_t a;
    asm("{ .reg .u64 t; cvta.to.shared.u64 t, %1; cvt.u32.u64 %0, t; }"
        : "=r"(a) : "l"(p));
    return a;
}

__device__ __forceinline__ void cp16(uint32_t s, const void* g) {
    asm volatile("cp.async.cg.shared.global [%0], [%1], 16;"
                 :: "r"(s), "l"(g) : "memory");
}

#define CP_COMMIT() asm volatile("cp.async.commit_group;" ::: "memory")
#define CP_WAIT1()  asm volatile("cp.async.wait_group 1;" ::: "memory")

__device__ __forceinline__ void ldm4(uint32_t* r, uint32_t addr) {
    asm volatile("ldmatrix.sync.aligned.m8n8.x4.shared.b16 {%0,%1,%2,%3}, [%4];"
                 : "=r"(r[0]), "=r"(r[1]), "=r"(r[2]), "=r"(r[3]) : "r"(addr));
}

__device__ __forceinline__ void mma16816(float* c, const uint32_t* a,
                                         const uint32_t* b) {
    asm volatile(
        "mma.sync.aligned.m16n8k16.row.col.f32.f16.f16.f32 "
        "{%0,%1,%2,%3}, {%4,%5,%6,%7}, {%8,%9}, {%0,%1,%2,%3};"
        : "+f"(c[0]), "+f"(c[1]), "+f"(c[2]), "+f"(c[3])
        : "r"(a[0]), "r"(a[1]), "r"(a[2]), "r"(a[3]), "r"(b[0]), "r"(b[1]));
}

// ----------------------------------------------------------------------------
// Prep (single kernel): fp16 weights + fp16 im2col of x
// ----------------------------------------------------------------------------
__global__ void prep_kernel(const float* __restrict__ x,
                            const float* __restrict__ w1) {
    int gid = blockIdx.x * 256 + threadIdx.x;
    const int nElems = P_TOT * K_TOT;
    if (gid < nElems) {
        g_B[gid] = __float2half_rn(w1[gid]);
    }
    gid -= nElems;
    if (gid < 0 || gid >= nElems) return;
    int p  = gid / K_TOT;
    int k  = gid - p * K_TOT;
    int c  = k / 9;
    int r9 = k - c * 9;
    int ky = r9 / 3;
    int kx = r9 - ky * 3;
    int b  = p >> 10;
    int y  = (p >> 5) & 31;
    int xx = p & 31;
    int iy = y + ky - 1;
    int ix = xx + kx - 1;
    float v = 0.0f;
    if ((unsigned)iy < 32u && (unsigned)ix < 32u)
        v = x[(((b << 7) + c) << 10) + (iy << 5) + ix];
    g_A[gid] = __float2half_rn(v);
}

// ----------------------------------------------------------------------------
// GEMM: 256 threads, 8 warps (2 row-warps x 4 col-warps), warp tile 64x64.
// Each warp-column owns exactly one output channel -> shuffle-only epilogue.
// ----------------------------------------------------------------------------
__global__ __launch_bounds__(256, 1)
void gemm_kernel(const float* __restrict__ b1, const float* __restrict__ w2,
                 const float* __restrict__ b2, float* __restrict__ out) {
    extern __shared__ char smem[];
    const uint32_t sb = smem_u32(smem);
    const int tid = threadIdx.x;
    const int wid = tid >> 5;
    const int lid = tid & 31;
    const int wr  = wid >> 2;        // 0..1  rows wr*64..+63
    const int wc  = wid & 3;         // 0..3  cols wc*64..+63  (= channel wc)
    const int ptile = blockIdx.x & 63;   // 64 position tiles
    const int ntile = blockIdx.x >> 6;   // 32 channel-group tiles

    float* b1s = (float*)(smem + CONST_OFF);          // 256
    float* w2f = (float*)(smem + CONST_OFF + 1024);   // 256
    float* b2f = (float*)(smem + CONST_OFF + 2048);   // 4

    b1s[tid] = b1[ntile * 256 + tid];
    w2f[tid] = w2[ntile * 256 + tid];
    if (tid < 4) b2f[tid] = b2[ntile * 4 + tid];

    const __half* Ag = g_A + (size_t)(ptile * BM) * K_TOT;
    const __half* Bg = g_B + (size_t)(ntile * BN) * K_TOT;
    const int r8 = tid >> 3, c8 = tid & 7;

    auto load_stage = [&](int ch, int slot) {
        const uint32_t sA = sb + slot * STAGE_BYTES;
        const uint32_t sB = sA + BM * 128;
        const __half* As = Ag + ch * BK;
        const __half* Bs = Bg + ch * BK;
        #pragma unroll
        for (int i = 0; i < 4; i++) {
            int r = r8 + i * 32;                       // A rows 0..127
            cp16(sA + r * 128 + ((c8 ^ (r & 7)) << 4),
                 As + (size_t)r * K_TOT + c8 * 8);
        }
        #pragma unroll
        for (int i = 0; i < 8; i++) {
            int r = r8 + i * 32;                       // B rows 0..255
            cp16(sB + r * 128 + ((c8 ^ (r & 7)) << 4),
                 Bs + (size_t)r * K_TOT + c8 * 8);
        }
    };

    load_stage(0, 0); CP_COMMIT();
    load_stage(1, 1); CP_COMMIT();

    float acc[4][8][4];
    #pragma unroll
    for (int i = 0; i < 4; i++)
        #pragma unroll
        for (int j = 0; j < 8; j++)
            #pragma unroll
            for (int e = 0; e < 4; e++) acc[i][j][e] = 0.0f;

    for (int ch = 0; ch < NCH; ch++) {
        CP_WAIT1();                 // chunk ch resident (<=1 group pending)
        __syncthreads();            // all warps done reading slot (ch+2)%3
        if (ch + 2 < NCH) load_stage(ch + 2, (ch + 2) % STAGES);
        CP_COMMIT();

        const uint32_t aBase = sb + (ch % STAGES) * STAGE_BYTES;
        const uint32_t bBase = aBase + BM * 128;

        #pragma unroll
        for (int ks = 0; ks < 4; ks++) {
            uint32_t a[4][4];
            #pragma unroll
            for (int mf = 0; mf < 4; mf++) {
                int ra = wr * 64 + mf * 16 + (lid & 15);
                uint32_t addr = aBase + ra * 128 +
                    ((((ks << 1) + (lid >> 4)) ^ (ra & 7)) << 4);
                ldm4(a[mf], addr);
            }
            uint32_t b[8][2];
            #pragma unroll
            for (int nf2 = 0; nf2 < 4; nf2++) {
                int rb = wc * 64 + nf2 * 16 + (lid & 7) + ((lid >> 4) << 3);
                uint32_t addr = bBase + rb * 128 +
                    ((((ks << 1) + ((lid >> 3) & 1)) ^ (rb & 7)) << 4);
                uint32_t t[4];
                ldm4(t, addr);
                b[nf2 * 2][0] = t[0]; b[nf2 * 2][1] = t[1];
                b[nf2 * 2 + 1][0] = t[2]; b[nf2 * 2 + 1][1] = t[3];
            }
            #pragma unroll
            for (int mf = 0; mf < 4; mf++)
                #pragma unroll
                for (int nf = 0; nf < 8; nf++)
                    mma16816(acc[mf][nf], a[mf], b[nf]);
        }
    }

    // ---------------- epilogue (shuffle-only; warp wc owns channel wc) -------
    // acc[mf][nf][e]: row = wr*64+mf*16+(lid>>2)+8*(e>>1)
    //                 col = wc*64+nf*8+2*(lid&3)+(e&1)  (mid = col - wc*64)
    const float bias2 = b2f[wc];
    #pragma unroll
    for (int mf = 0; mf < 4; mf++) {
        #pragma unroll
        for (int rh = 0; rh < 2; rh++) {
            float p = 0.0f;
            #pragma unroll
            for (int nf = 0; nf < 8; nf++) {
                #pragma unroll
                for (int cc = 0; cc < 2; cc++) {
                    int nt = wc * 64 + nf * 8 + (lid & 3) * 2 + cc;
                    float v = acc[mf][nf][rh * 2 + cc] + b1s[nt];
                    v = (v < 0.0f) ? 0.1f * v : v;
                    p = fmaf(w2f[nt], v, p);
                }
            }
            p += __shfl_xor_sync(0xFFFFFFFFu, p, 1);
            p += __shfl_xor_sync(0xFFFFFFFFu, p, 2);
            if ((lid & 3) == 0) {
                int row = wr * 64 + mf * 16 + (lid >> 2) + rh * 8;
                int pg  = ptile * BM + row;
                int o   = ntile * 4 + wc;
                out[(size_t)((pg >> 10) * 128 + o) * 1024 + (pg & 1023)]
                    = p + bias2;
            }
        }
    }
}

// ----------------------------------------------------------------------------
extern "C" void kernel_launch(void* const* d_in, const int* in_sizes, int n_in,
                              void* d_out, int out_size) {
    const float* x  = (const float*)d_in[0];
    const float* w1 = (const float*)d_in[1];
    const float* b1 = (const float*)d_in[2];
    const float* w2 = (const float*)d_in[3];
    const float* b2 = (const float*)d_in[4];
    float* out = (float*)d_out;

    cudaFuncSetAttribute(gemm_kernel, cudaFuncAttributeMaxDynamicSharedMemorySize,
                         SMEM_BYTES);

    const int nElems = P_TOT * K_TOT;
    const int blocks = (2 * nElems + 255) / 256;
    prep_kernel<<<blocks, 256>>>(x, w1);
    gemm_kernel<<<64 * 32, 256, SMEM_BYTES>>>(b1, w2, b2, out);
}

// round 7
// speedup vs baseline: 1.1145x; 1.1145x over previous
#include <cuda_runtime.h>
#include <cuda_fp16.h>
#include <cstdint>
#include <cstddef>

// ----------------------------------------------------------------------------
// ThickConv2d as one fp16 mma.sync GEMM:
//   A (im2col of x, fp16) [8192 x 1152] @ W1^T (fp16) [1152 x 8192]
//   fp32 accum -> epilogue: +b1, leaky(0.1), 64-wide w2 contraction, +b2
// R6: CTA 128x128 with 128 threads (4 warps 2x2), warp tile 64x64,
//     3-stage cp.async, 2 CTAs/SM (decoupled barriers + latency hiding).
// ----------------------------------------------------------------------------

#define P_TOT   8192
#define K_TOT   1152
#define N_TOT   8192
#define BM      128
#define BN      128           // = 2 output channels x 64 mid
#define BK      64            // halves per chunk (128B rows)
#define NCH     18            // 1152/64
#define STAGES  3
#define STAGE_BYTES ((BM + BN) * 128)            // 32768
#define CONST_OFF   (STAGES * STAGE_BYTES)       // 98304
#define SMEM_BYTES  (CONST_OFF + 512 + 512 + 16)

__device__ __half g_A[(size_t)P_TOT * K_TOT];
__device__ __half g_B[(size_t)N_TOT * K_TOT];

__device__ __forceinline__ uint32_t smem_u32(const void* p) {
    uint32_t a;
    asm("{ .reg .u64 t; cvta.to.shared.u64 t, %1; cvt.u32.u64 %0, t; }"
        : "=r"(a) : "l"(p));
    return a;
}

__device__ __forceinline__ void cp16(uint32_t s, const void* g) {
    asm volatile("cp.async.cg.shared.global [%0], [%1], 16;"
                 :: "r"(s), "l"(g) : "memory");
}

#define CP_COMMIT() asm volatile("cp.async.commit_group;" ::: "memory")
#define CP_WAIT1()  asm volatile("cp.async.wait_group 1;" ::: "memory")

__device__ __forceinline__ void ldm4(uint32_t* r, uint32_t addr) {
    asm volatile("ldmatrix.sync.aligned.m8n8.x4.shared.b16 {%0,%1,%2,%3}, [%4];"
                 : "=r"(r[0]), "=r"(r[1]), "=r"(r[2]), "=r"(r[3]) : "r"(addr));
}

__device__ __forceinline__ void mma16816(float* c, const uint32_t* a,
                                         const uint32_t* b) {
    asm volatile(
        "mma.sync.aligned.m16n8k16.row.col.f32.f16.f16.f32 "
        "{%0,%1,%2,%3}, {%4,%5,%6,%7}, {%8,%9}, {%0,%1,%2,%3};"
        : "+f"(c[0]), "+f"(c[1]), "+f"(c[2]), "+f"(c[3])
        : "r"(a[0]), "r"(a[1]), "r"(a[2]), "r"(a[3]), "r"(b[0]), "r"(b[1]));
}

// ----------------------------------------------------------------------------
// Prep (single kernel): fp16 weights + fp16 im2col of x
// ----------------------------------------------------------------------------
__global__ void prep_kernel(const float* __restrict__ x,
                            const float* __restrict__ w1) {
    int gid = blockIdx.x * 256 + threadIdx.x;
    const int nElems = P_TOT * K_TOT;
    if (gid < nElems) {
        g_B[gid] = __float2half_rn(w1[gid]);
    }
    gid -= nElems;
    if (gid < 0 || gid >= nElems) return;
    int p  = gid / K_TOT;
    int k  = gid - p * K_TOT;
    int c  = k / 9;
    int r9 = k - c * 9;
    int ky = r9 / 3;
    int kx = r9 - ky * 3;
    int b  = p >> 10;
    int y  = (p >> 5) & 31;
    int xx = p & 31;
    int iy = y + ky - 1;
    int ix = xx + kx - 1;
    float v = 0.0f;
    if ((unsigned)iy < 32u && (unsigned)ix < 32u)
        v = x[(((b << 7) + c) << 10) + (iy << 5) + ix];
    g_A[gid] = __float2half_rn(v);
}

// ----------------------------------------------------------------------------
// GEMM: 128 threads, 4 warps (2 row-warps x 2 col-warps), warp tile 64x64.
// 2 CTAs/SM. Each warp-column owns one output channel -> shuffle-only epilogue.
// ----------------------------------------------------------------------------
__global__ __launch_bounds__(128, 2)
void gemm_kernel(const float* __restrict__ b1, const float* __restrict__ w2,
                 const float* __restrict__ b2, float* __restrict__ out) {
    extern __shared__ char smem[];
    const uint32_t sb = smem_u32(smem);
    const int tid = threadIdx.x;
    const int wid = tid >> 5;
    const int lid = tid & 31;
    const int wr  = wid >> 1;        // 0..1  rows wr*64..+63
    const int wc  = wid & 1;         // 0..1  cols wc*64..+63 (= channel wc)
    const int ptile = blockIdx.x & 63;   // 64 position tiles
    const int ntile = blockIdx.x >> 6;   // 64 channel-pair tiles

    float* b1s = (float*)(smem + CONST_OFF);          // 128
    float* w2f = (float*)(smem + CONST_OFF + 512);    // 128
    float* b2f = (float*)(smem + CONST_OFF + 1024);   // 2

    b1s[tid] = b1[ntile * 128 + tid];
    w2f[tid] = w2[ntile * 128 + tid];
    if (tid < 2) b2f[tid] = b2[ntile * 2 + tid];

    const __half* Ag = g_A + (size_t)(ptile * BM) * K_TOT;
    const __half* Bg = g_B + (size_t)(ntile * BN) * K_TOT;
    const int r8 = tid >> 3, c8 = tid & 7;            // r8: 0..15

    auto load_stage = [&](int ch, int slot) {
        const uint32_t sA = sb + slot * STAGE_BYTES;
        const uint32_t sB = sA + BM * 128;
        const __half* As = Ag + ch * BK;
        const __half* Bs = Bg + ch * BK;
        #pragma unroll
        for (int i = 0; i < 8; i++) {
            int r = r8 + i * 16;                      // A rows 0..127
            cp16(sA + r * 128 + ((c8 ^ (r & 7)) << 4),
                 As + (size_t)r * K_TOT + c8 * 8);
        }
        #pragma unroll
        for (int i = 0; i < 8; i++) {
            int r = r8 + i * 16;                      // B rows 0..127
            cp16(sB + r * 128 + ((c8 ^ (r & 7)) << 4),
                 Bs + (size_t)r * K_TOT + c8 * 8);
        }
    };

    load_stage(0, 0); CP_COMMIT();
    load_stage(1, 1); CP_COMMIT();

    float acc[4][8][4];
    #pragma unroll
    for (int i = 0; i < 4; i++)
        #pragma unroll
        for (int j = 0; j < 8; j++)
            #pragma unroll
            for (int e = 0; e < 4; e++) acc[i][j][e] = 0.0f;

    for (int ch = 0; ch < NCH; ch++) {
        CP_WAIT1();                 // chunk ch resident (<=1 group pending)
        __syncthreads();            // visibility + done reading slot (ch+2)%3
        if (ch + 2 < NCH) load_stage(ch + 2, (ch + 2) % STAGES);
        CP_COMMIT();

        const uint32_t aBase = sb + (ch % STAGES) * STAGE_BYTES;
        const uint32_t bBase = aBase + BM * 128;

        #pragma unroll
        for (int ks = 0; ks < 4; ks++) {
            uint32_t a[4][4];
            #pragma unroll
            for (int mf = 0; mf < 4; mf++) {
                int ra = wr * 64 + mf * 16 + (lid & 15);
                uint32_t addr = aBase + ra * 128 +
                    ((((ks << 1) + (lid >> 4)) ^ (ra & 7)) << 4);
                ldm4(a[mf], addr);
            }
            uint32_t b[8][2];
            #pragma unroll
            for (int nf2 = 0; nf2 < 4; nf2++) {
                int rb = wc * 64 + nf2 * 16 + (lid & 7) + ((lid >> 4) << 3);
                uint32_t addr = bBase + rb * 128 +
                    ((((ks << 1) + ((lid >> 3) & 1)) ^ (rb & 7)) << 4);
                uint32_t t[4];
                ldm4(t, addr);
                b[nf2 * 2][0] = t[0]; b[nf2 * 2][1] = t[1];
                b[nf2 * 2 + 1][0] = t[2]; b[nf2 * 2 + 1][1] = t[3];
            }
            #pragma unroll
            for (int mf = 0; mf < 4; mf++)
                #pragma unroll
                for (int nf = 0; nf < 8; nf++)
                    mma16816(acc[mf][nf], a[mf], b[nf]);
        }
    }

    // ---------------- epilogue (shuffle-only; warp wc owns channel wc) -------
    // acc[mf][nf][e]: row = wr*64+mf*16+(lid>>2)+8*(e>>1)
    //                 col = wc*64+nf*8+2*(lid&3)+(e&1)
    const float bias2 = b2f[wc];
    #pragma unroll
    for (int mf = 0; mf < 4; mf++) {
        #pragma unroll
        for (int rh = 0; rh < 2; rh++) {
            float p = 0.0f;
            #pragma unroll
            for (int nf = 0; nf < 8; nf++) {
                #pragma unroll
                for (int cc = 0; cc < 2; cc++) {
                    int nt = wc * 64 + nf * 8 + (lid & 3) * 2 + cc;
                    float v = acc[mf][nf][rh * 2 + cc] + b1s[nt];
                    v = (v < 0.0f) ? 0.1f * v : v;
                    p = fmaf(w2f[nt], v, p);
                }
            }
            p += __shfl_xor_sync(0xFFFFFFFFu, p, 1);
            p += __shfl_xor_sync(0xFFFFFFFFu, p, 2);
            if ((lid & 3) == 0) {
                int row = wr * 64 + mf * 16 + (lid >> 2) + rh * 8;
                int pg  = ptile * BM + row;
                int o   = ntile * 2 + wc;
                out[(size_t)((pg >> 10) * 128 + o) * 1024 + (pg & 1023)]
                    = p + bias2;
            }
        }
    }
}

// ----------------------------------------------------------------------------
extern "C" void kernel_launch(void* const* d_in, const int* in_sizes, int n_in,
                              void* d_out, int out_size) {
    const float* x  = (const float*)d_in[0];
    const float* w1 = (const float*)d_in[1];
    const float* b1 = (const float*)d_in[2];
    const float* w2 = (const float*)d_in[3];
    const float* b2 = (const float*)d_in[4];
    float* out = (float*)d_out;

    cudaFuncSetAttribute(gemm_kernel, cudaFuncAttributeMaxDynamicSharedMemorySize,
                         SMEM_BYTES);

    const int nElems = P_TOT * K_TOT;
    const int blocks = (2 * nElems + 255) / 256;
    prep_kernel<<<blocks, 256>>>(x, w1);
    gemm_kernel<<<64 * 64, 128, SMEM_BYTES>>>(b1, w2, b2, out);
}

// round 8
// speedup vs baseline: 1.1555x; 1.0368x over previous
#include <cuda_runtime.h>
#include <cuda_fp16.h>
#include <cstdint>
#include <cstddef>

// ----------------------------------------------------------------------------
// ThickConv2d as one fp16 mma.sync GEMM:
//   A (im2col of x, fp16) [8192 x 1152] @ W1^T (fp16) [1152 x 8192]
//   fp32 accum -> epilogue: +b1, leaky(0.1), 64-wide w2 contraction, +b2
// R7: CTA 128x128, 4 warps (2x2), warp tile 64x64, 2 CTAs/SM, 3-stage
//     cp.async + DOUBLE-BUFFERED REGISTER FRAGMENTS (LDSM for ks+1 issued
//     ahead of ks's MMAs). Vectorized weight prep.
// ----------------------------------------------------------------------------

#define P_TOT   8192
#define K_TOT   1152
#define N_TOT   8192
#define BM      128
#define BN      128           // = 2 output channels x 64 mid
#define BK      64            // halves per chunk (128B rows)
#define NCH     18            // 1152/64
#define STAGES  3
#define STAGE_BYTES ((BM + BN) * 128)            // 32768
#define CONST_OFF   (STAGES * STAGE_BYTES)       // 98304
#define SMEM_BYTES  (CONST_OFF + 512 + 512 + 16)

__device__ __half g_A[(size_t)P_TOT * K_TOT];
__device__ __half g_B[(size_t)N_TOT * K_TOT];

__device__ __forceinline__ uint32_t smem_u32(const void* p) {
    uint32_t a;
    asm("{ .reg .u64 t; cvta.to.shared.u64 t, %1; cvt.u32.u64 %0, t; }"
        : "=r"(a) : "l"(p));
    return a;
}

__device__ __forceinline__ void cp16(uint32_t s, const void* g) {
    asm volatile("cp.async.cg.shared.global [%0], [%1], 16;"
                 :: "r"(s), "l"(g) : "memory");
}

#define CP_COMMIT() asm volatile("cp.async.commit_group;" ::: "memory")
#define CP_WAIT1()  asm volatile("cp.async.wait_group 1;" ::: "memory")

__device__ __forceinline__ void ldm4(uint32_t* r, uint32_t addr) {
    asm volatile("ldmatrix.sync.aligned.m8n8.x4.shared.b16 {%0,%1,%2,%3}, [%4];"
                 : "=r"(r[0]), "=r"(r[1]), "=r"(r[2]), "=r"(r[3]) : "r"(addr));
}

__device__ __forceinline__ void mma16816(float* c, const uint32_t* a,
                                         const uint32_t* b) {
    asm volatile(
        "mma.sync.aligned.m16n8k16.row.col.f32.f16.f16.f32 "
        "{%0,%1,%2,%3}, {%4,%5,%6,%7}, {%8,%9}, {%0,%1,%2,%3};"
        : "+f"(c[0]), "+f"(c[1]), "+f"(c[2]), "+f"(c[3])
        : "r"(a[0]), "r"(a[1]), "r"(a[2]), "r"(a[3]), "r"(b[0]), "r"(b[1]));
}

// ----------------------------------------------------------------------------
// Prep (single launch, split grid): vectorized fp16 weights + scalar im2col.
// ----------------------------------------------------------------------------
#define NELEMS   (P_TOT * K_TOT)
#define WBLOCKS  (NELEMS / 8 / 256)              // 4608 (vector-of-8 per thread)

__global__ void prep_kernel(const float* __restrict__ x,
                            const float* __restrict__ w1) {
    if (blockIdx.x < WBLOCKS) {
        int i = blockIdx.x * 256 + threadIdx.x;      // 8 elements per thread
        float4 f0 = ((const float4*)w1)[2 * i];
        float4 f1 = ((const float4*)w1)[2 * i + 1];
        __half2 h0 = __floats2half2_rn(f0.x, f0.y);
        __half2 h1 = __floats2half2_rn(f0.z, f0.w);
        __half2 h2 = __floats2half2_rn(f1.x, f1.y);
        __half2 h3 = __floats2half2_rn(f1.z, f1.w);
        uint4 v;
        v.x = *(uint32_t*)&h0; v.y = *(uint32_t*)&h1;
        v.z = *(uint32_t*)&h2; v.w = *(uint32_t*)&h3;
        ((uint4*)g_B)[i] = v;
        return;
    }
    int gid = (blockIdx.x - WBLOCKS) * 256 + threadIdx.x;
    if (gid >= NELEMS) return;
    int p  = gid / K_TOT;
    int k  = gid - p * K_TOT;          // k = c*9 + ky*3 + kx (matches w1)
    int c  = k / 9;
    int r9 = k - c * 9;
    int ky = r9 / 3;
    int kx = r9 - ky * 3;
    int b  = p >> 10;
    int y  = (p >> 5) & 31;
    int xx = p & 31;
    int iy = y + ky - 1;
    int ix = xx + kx - 1;
    float v = 0.0f;
    if ((unsigned)iy < 32u && (unsigned)ix < 32u)
        v = x[(((b << 7) + c) << 10) + (iy << 5) + ix];
    g_A[gid] = __float2half_rn(v);
}

// ----------------------------------------------------------------------------
// GEMM: 128 threads, 4 warps (2 row x 2 col), warp tile 64x64, 2 CTAs/SM.
// ----------------------------------------------------------------------------
__global__ __launch_bounds__(128, 2)
void gemm_kernel(const float* __restrict__ b1, const float* __restrict__ w2,
                 const float* __restrict__ b2, float* __restrict__ out) {
    extern __shared__ char smem[];
    const uint32_t sb = smem_u32(smem);
    const int tid = threadIdx.x;
    const int wid = tid >> 5;
    const int lid = tid & 31;
    const int wr  = wid >> 1;        // 0..1  rows wr*64..+63
    const int wc  = wid & 1;         // 0..1  cols wc*64..+63 (= channel wc)
    const int ptile = blockIdx.x & 63;
    const int ntile = blockIdx.x >> 6;

    float* b1s = (float*)(smem + CONST_OFF);
    float* w2f = (float*)(smem + CONST_OFF + 512);
    float* b2f = (float*)(smem + CONST_OFF + 1024);

    b1s[tid] = b1[ntile * 128 + tid];
    w2f[tid] = w2[ntile * 128 + tid];
    if (tid < 2) b2f[tid] = b2[ntile * 2 + tid];

    const __half* Ag = g_A + (size_t)(ptile * BM) * K_TOT;
    const __half* Bg = g_B + (size_t)(ntile * BN) * K_TOT;
    const int r8 = tid >> 3, c8 = tid & 7;

    auto load_stage = [&](int ch, int slot) {
        const uint32_t sA = sb + slot * STAGE_BYTES;
        const uint32_t sB = sA + BM * 128;
        const __half* As = Ag + ch * BK;
        const __half* Bs = Bg + ch * BK;
        #pragma unroll
        for (int i = 0; i < 8; i++) {
            int r = r8 + i * 16;
            cp16(sA + r * 128 + ((c8 ^ (r & 7)) << 4),
                 As + (size_t)r * K_TOT + c8 * 8);
        }
        #pragma unroll
        for (int i = 0; i < 8; i++) {
            int r = r8 + i * 16;
            cp16(sB + r * 128 + ((c8 ^ (r & 7)) << 4),
                 Bs + (size_t)r * K_TOT + c8 * 8);
        }
    };

    load_stage(0, 0); CP_COMMIT();
    load_stage(1, 1); CP_COMMIT();

    float acc[4][8][4];
    #pragma unroll
    for (int i = 0; i < 4; i++)
        #pragma unroll
        for (int j = 0; j < 8; j++)
            #pragma unroll
            for (int e = 0; e < 4; e++) acc[i][j][e] = 0.0f;

    uint32_t afrag[2][4][4];
    uint32_t bfrag[2][8][2];

    // Fragment loader for one ks step into buffer bi.
    const int raLo = wr * 64 + (lid & 15);             // + mf*16
    const int rbLo = wc * 64 + (lid & 7) + ((lid >> 4) << 3);  // + nf2*16
    auto load_frags = [&](uint32_t aBase, uint32_t bBase, int ks, int bi) {
        #pragma unroll
        for (int mf = 0; mf < 4; mf++) {
            int ra = raLo + mf * 16;
            uint32_t addr = aBase + ra * 128 +
                ((((ks << 1) + (lid >> 4)) ^ (ra & 7)) << 4);
            ldm4(afrag[bi][mf], addr);
        }
        #pragma unroll
        for (int nf2 = 0; nf2 < 4; nf2++) {
            int rb = rbLo + nf2 * 16;
            uint32_t addr = bBase + rb * 128 +
                ((((ks << 1) + ((lid >> 3) & 1)) ^ (rb & 7)) << 4);
            uint32_t t[4];
            ldm4(t, addr);
            bfrag[bi][nf2 * 2][0] = t[0]; bfrag[bi][nf2 * 2][1] = t[1];
            bfrag[bi][nf2 * 2 + 1][0] = t[2]; bfrag[bi][nf2 * 2 + 1][1] = t[3];
        }
    };

    for (int ch = 0; ch < NCH; ch++) {
        CP_WAIT1();                 // chunk ch resident (<=1 group pending)
        __syncthreads();            // all warps done reading slot (ch+2)%3
        if (ch + 2 < NCH) load_stage(ch + 2, (ch + 2) % STAGES);
        CP_COMMIT();

        const uint32_t aBase = sb + (ch % STAGES) * STAGE_BYTES;
        const uint32_t bBase = aBase + BM * 128;

        load_frags(aBase, bBase, 0, 0);
        #pragma unroll
        for (int ks = 0; ks < 4; ks++) {
            if (ks < 3) load_frags(aBase, bBase, ks + 1, (ks + 1) & 1);
            const int cur = ks & 1;
            #pragma unroll
            for (int mf = 0; mf < 4; mf++)
                #pragma unroll
                for (int nf = 0; nf < 8; nf++)
                    mma16816(acc[mf][nf], afrag[cur][mf], bfrag[cur][nf]);
        }
    }

    // ---------------- epilogue (shuffle-only; warp wc owns channel wc) -------
    const float bias2 = b2f[wc];
    #pragma unroll
    for (int mf = 0; mf < 4; mf++) {
        #pragma unroll
        for (int rh = 0; rh < 2; rh++) {
            float p = 0.0f;
            #pragma unroll
            for (int nf = 0; nf < 8; nf++) {
                #pragma unroll
                for (int cc = 0; cc < 2; cc++) {
                    int nt = wc * 64 + nf * 8 + (lid & 3) * 2 + cc;
                    float v = acc[mf][nf][rh * 2 + cc] + b1s[nt];
                    v = (v < 0.0f) ? 0.1f * v : v;
                    p = fmaf(w2f[nt], v, p);
                }
            }
            p += __shfl_xor_sync(0xFFFFFFFFu, p, 1);
            p += __shfl_xor_sync(0xFFFFFFFFu, p, 2);
            if ((lid & 3) == 0) {
                int row = wr * 64 + mf * 16 + (lid >> 2) + rh * 8;
                int pg  = ptile * BM + row;
                int o   = ntile * 2 + wc;
                out[(size_t)((pg >> 10) * 128 + o) * 1024 + (pg & 1023)]
                    = p + bias2;
            }
        }
    }
}

// ----------------------------------------------------------------------------
extern "C" void kernel_launch(void* const* d_in, const int* in_sizes, int n_in,
                              void* d_out, int out_size) {
    const float* x  = (const float*)d_in[0];
    const float* w1 = (const float*)d_in[1];
    const float* b1 = (const float*)d_in[2];
    const float* w2 = (const float*)d_in[3];
    const float* b2 = (const float*)d_in[4];
    float* out = (float*)d_out;

    cudaFuncSetAttribute(gemm_kernel, cudaFuncAttributeMaxDynamicSharedMemorySize,
                         SMEM_BYTES);

    const int aBlocks = (NELEMS + 255) / 256;      // 36864
    prep_kernel<<<WBLOCKS + aBlocks, 256>>>(x, w1);
    gemm_kernel<<<64 * 64, 128, SMEM_BYTES>>>(b1, w2, b2, out);
}

// round 9
// speedup vs baseline: 1.7162x; 1.4853x over previous
#include <cuda_runtime.h>
#include <cuda_fp16.h>
#include <cstdint>
#include <cstddef>

// ----------------------------------------------------------------------------
// ThickConv2d via Winograd F(2x2,3x3):  2.25x fewer tensor MACs.
//   V[t][m][c] = input transform of x   (t=0..15, m=2048 tiles, c=128)
//   U[t][n][c] = weight transform of w1 (n=8192)
//   For each (m,n): M~[t] = sum_c V*U ; Y[2][2] = A^T M~ A  (A entries 0/+-1)
//   epilogue: +b1, leaky(0.1), 64-wide w2 contraction, +b2
// ----------------------------------------------------------------------------

#define CIN     128
#define NCHAN   8192          // OUT_CH*MID_CH
#define MT      2048          // 8 batches * 16*16 tiles
#define NT_CTA  128           // n per CTA (= 2 output channels)
#define MT_CTA  32            // m-tiles per CTA

#define VSTAGE  (MT_CTA * 256)        // 8192  (32 rows x 256B)
#define USTAGE  (NT_CTA * 256)        // 32768 (128 rows x 256B)
#define STAGE_B (VSTAGE + USTAGE)     // 40960
#define SM_B1   (2 * STAGE_B)         // 81920
#define SM_W2   (SM_B1 + 512)
#define SM_B2   (SM_W2 + 512)
#define SM_PART (SM_B2 + 32)
#define SMEM_BYTES (SM_PART + 4 * 128 * 4)   // + part[4][128]

__device__ __half g_V[(size_t)16 * MT * CIN];      //  8 MB
__device__ __half g_U[(size_t)16 * NCHAN * CIN];   // 32 MB

__device__ __forceinline__ uint32_t smem_u32(const void* p) {
    uint32_t a;
    asm("{ .reg .u64 t; cvta.to.shared.u64 t, %1; cvt.u32.u64 %0, t; }"
        : "=r"(a) : "l"(p));
    return a;
}

__device__ __forceinline__ void cp16(uint32_t s, const void* g) {
    asm volatile("cp.async.cg.shared.global [%0], [%1], 16;"
                 :: "r"(s), "l"(g) : "memory");
}

#define CP_COMMIT() asm volatile("cp.async.commit_group;" ::: "memory")
#define CP_WAIT0()  asm volatile("cp.async.wait_group 0;" ::: "memory")

__device__ __forceinline__ void ldm4(uint32_t* r, uint32_t addr) {
    asm volatile("ldmatrix.sync.aligned.m8n8.x4.shared.b16 {%0,%1,%2,%3}, [%4];"
                 : "=r"(r[0]), "=r"(r[1]), "=r"(r[2]), "=r"(r[3]) : "r"(addr));
}

__device__ __forceinline__ void mma16816(float* c, const uint32_t* a,
                                         const uint32_t* b) {
    asm volatile(
        "mma.sync.aligned.m16n8k16.row.col.f32.f16.f16.f32 "
        "{%0,%1,%2,%3}, {%4,%5,%6,%7}, {%8,%9}, {%0,%1,%2,%3};"
        : "+f"(c[0]), "+f"(c[1]), "+f"(c[2]), "+f"(c[3])
        : "r"(a[0]), "r"(a[1]), "r"(a[2]), "r"(a[3]), "r"(b[0]), "r"(b[1]));
}

// ----------------------------------------------------------------------------
// Transforms (fp32 math, fp16 store).  Blocks [0,1024): input; rest: weight.
// ----------------------------------------------------------------------------
#define IN_BLOCKS (MT * CIN / 256)          // 1024
#define W_BLOCKS  (NCHAN * CIN / 256)       // 4096

__global__ void wino_prep(const float* __restrict__ x,
                          const float* __restrict__ w1) {
    if (blockIdx.x < IN_BLOCKS) {
        // ---- input transform: V = B^T d B ----
        int gid = blockIdx.x * 256 + threadIdx.x;     // m*128 + c
        int m = gid >> 7, c = gid & 127;
        int b = m >> 8, ty = (m >> 4) & 15, tx = m & 15;
        const float* xp = x + (((size_t)b * 128 + c) << 10);
        int iy0 = ty * 2 - 1, ix0 = tx * 2 - 1;
        float d[4][4];
        #pragma unroll
        for (int i = 0; i < 4; i++)
            #pragma unroll
            for (int j = 0; j < 4; j++) {
                int iy = iy0 + i, ix = ix0 + j;
                d[i][j] = ((unsigned)iy < 32u && (unsigned)ix < 32u)
                          ? xp[iy * 32 + ix] : 0.0f;
            }
        float tm[4][4], v[4][4];
        #pragma unroll
        for (int j = 0; j < 4; j++) {
            tm[0][j] = d[0][j] - d[2][j];
            tm[1][j] = d[1][j] + d[2][j];
            tm[2][j] = d[2][j] - d[1][j];
            tm[3][j] = d[1][j] - d[3][j];
        }
        #pragma unroll
        for (int i = 0; i < 4; i++) {
            v[i][0] = tm[i][0] - tm[i][2];
            v[i][1] = tm[i][1] + tm[i][2];
            v[i][2] = tm[i][2] - tm[i][1];
            v[i][3] = tm[i][1] - tm[i][3];
        }
        #pragma unroll
        for (int t = 0; t < 16; t++)
            g_V[((size_t)t * MT + m) * CIN + c] = __float2half_rn(v[t >> 2][t & 3]);
        return;
    }
    // ---- weight transform: U = G g G^T ----
    int gid = (blockIdx.x - IN_BLOCKS) * 256 + threadIdx.x;  // n*128 + c
    int n = gid >> 7, c = gid & 127;
    const float* wp = w1 + ((size_t)n * 128 + c) * 9;
    float g[3][3];
    #pragma unroll
    for (int i = 0; i < 3; i++)
        #pragma unroll
        for (int j = 0; j < 3; j++) g[i][j] = wp[i * 3 + j];
    float gg[4][3], u[4][4];
    #pragma unroll
    for (int j = 0; j < 3; j++) {
        gg[0][j] = g[0][j];
        gg[1][j] = 0.5f * (g[0][j] + g[1][j] + g[2][j]);
        gg[2][j] = 0.5f * (g[0][j] - g[1][j] + g[2][j]);
        gg[3][j] = g[2][j];
    }
    #pragma unroll
    for (int i = 0; i < 4; i++) {
        u[i][0] = gg[i][0];
        u[i][1] = 0.5f * (gg[i][0] + gg[i][1] + gg[i][2]);
        u[i][2] = 0.5f * (gg[i][0] - gg[i][1] + gg[i][2]);
        u[i][3] = gg[i][2];
    }
    #pragma unroll
    for (int t = 0; t < 16; t++)
        g_U[((size_t)t * NCHAN + n) * CIN + c] = __float2half_rn(u[t >> 2][t & 3]);
}

// ----------------------------------------------------------------------------
// Winograd GEMM + inverse transform + fused epilogue.
// 128 threads, 4 warps split over N (warp tile 32 m-tiles x 32 n), K=128 per t.
// ----------------------------------------------------------------------------
__global__ __launch_bounds__(128, 2)
void wino_gemm(const float* __restrict__ b1, const float* __restrict__ w2,
               const float* __restrict__ b2, float* __restrict__ out) {
    extern __shared__ char smem[];
    const uint32_t sb = smem_u32(smem);
    const int tid = threadIdx.x;
    const int wn  = tid >> 5;          // warp 0..3: n-range wn*32..+31
    const int lid = tid & 31;
    const int ptile = blockIdx.x & 63;     // 64 m-tile groups
    const int ntile = blockIdx.x >> 6;     // 64 n groups (2 channels each)

    float* b1s  = (float*)(smem + SM_B1);
    float* w2f  = (float*)(smem + SM_W2);
    float* b2f  = (float*)(smem + SM_B2);
    float* part = (float*)(smem + SM_PART);   // [4 warps][128]

    b1s[tid] = b1[ntile * 128 + tid];
    w2f[tid] = w2[ntile * 128 + tid];
    if (tid < 2) b2f[tid] = b2[ntile * 2 + tid];

    const int r5 = tid >> 4, u5 = tid & 15;   // loader: (row, 16B-chunk)

    auto load_stage = [&](int t, int slot) {
        const uint32_t sV = sb + slot * STAGE_B;
        const uint32_t sU = sV + VSTAGE;
        const __half* Vg = g_V + ((size_t)t * MT + ptile * MT_CTA) * CIN;
        const __half* Ug = g_U + ((size_t)t * NCHAN + ntile * NT_CTA) * CIN;
        #pragma unroll
        for (int i = 0; i < 4; i++) {          // V: 32 rows x 16 chunks
            int r = r5 + i * 8;
            cp16(sV + r * 256 + ((u5 ^ (r & 7)) << 4),
                 Vg + (size_t)r * CIN + u5 * 8);
        }
        #pragma unroll
        for (int i = 0; i < 16; i++) {         // U: 128 rows x 16 chunks
            int r = r5 + i * 8;
            cp16(sU + r * 256 + ((u5 ^ (r & 7)) << 4),
                 Ug + (size_t)r * CIN + u5 * 8);
        }
    };

    load_stage(0, 0); CP_COMMIT();

    float acc[2][2][2][4][4];   // [p][q][mf][nf][e]
    #pragma unroll
    for (int p = 0; p < 2; p++)
        #pragma unroll
        for (int q = 0; q < 2; q++)
            #pragma unroll
            for (int mf = 0; mf < 2; mf++)
                #pragma unroll
                for (int nf = 0; nf < 4; nf++)
                    #pragma unroll
                    for (int e = 0; e < 4; e++) acc[p][q][mf][nf][e] = 0.0f;

    const int raLo = (lid & 15);                          // + mf*16
    const int rbLo = wn * 32 + (lid & 7) + ((lid >> 4) << 3);  // + nf2*16
    constexpr int ATc[2][4] = {{1, 1, 1, 0}, {0, 1, -1, -1}};

    #pragma unroll
    for (int t = 0; t < 16; t++) {
        CP_WAIT0();               // stage for t resident
        __syncthreads();          // everyone done reading stage t-1
        if (t + 1 < 16) { load_stage(t + 1, (t + 1) & 1); }
        CP_COMMIT();

        const uint32_t vBase = sb + (t & 1) * STAGE_B;
        const uint32_t uBase = vBase + VSTAGE;

        float prod[2][4][4] = {};
        #pragma unroll 1
        for (int ks = 0; ks < 8; ks++) {
            uint32_t a[2][4];
            #pragma unroll
            for (int mf = 0; mf < 2; mf++) {
                int ra = raLo + mf * 16;
                ldm4(a[mf], vBase + ra * 256 +
                     ((((ks << 1) + (lid >> 4)) ^ (ra & 7)) << 4));
            }
            uint32_t b[4][2];
            #pragma unroll
            for (int nf2 = 0; nf2 < 2; nf2++) {
                int rb = rbLo + nf2 * 16;
                uint32_t tt[4];
                ldm4(tt, uBase + rb * 256 +
                     ((((ks << 1) + ((lid >> 3) & 1)) ^ (rb & 7)) << 4));
                b[nf2 * 2][0] = tt[0]; b[nf2 * 2][1] = tt[1];
                b[nf2 * 2 + 1][0] = tt[2]; b[nf2 * 2 + 1][1] = tt[3];
            }
            #pragma unroll
            for (int mf = 0; mf < 2; mf++)
                #pragma unroll
                for (int nf = 0; nf < 4; nf++)
                    mma16816(prod[mf][nf], a[mf], b[nf]);
        }

        // inverse-transform accumulate (A entries 0/+-1 -> pure add/sub)
        const int ti = t >> 2, tj = t & 3;
        #pragma unroll
        for (int p = 0; p < 2; p++) {
            if (ATc[p][ti] == 0) continue;
            #pragma unroll
            for (int q = 0; q < 2; q++) {
                if (ATc[q][tj] == 0) continue;
                const float s = (float)(ATc[p][ti] * ATc[q][tj]);
                #pragma unroll
                for (int mf = 0; mf < 2; mf++)
                    #pragma unroll
                    for (int nf = 0; nf < 4; nf++)
                        #pragma unroll
                        for (int e = 0; e < 4; e++)
                            acc[p][q][mf][nf][e] += s * prod[mf][nf][e];
            }
        }
    }

    // ---------------- epilogue ----------------
    // value (mf,nf,e): m-row = mf*16 + (lid>>2) + 8*(e>>1)
    //                  CTA-n = wn*32 + nf*8 + 2*(lid&3) + (e&1)
    #pragma unroll
    for (int p = 0; p < 2; p++) {
        #pragma unroll
        for (int q = 0; q < 2; q++) {
            #pragma unroll
            for (int mf = 0; mf < 2; mf++) {
                #pragma unroll
                for (int rh = 0; rh < 2; rh++) {
                    float s = 0.0f;
                    #pragma unroll
                    for (int nf = 0; nf < 4; nf++) {
                        #pragma unroll
                        for (int cc = 0; cc < 2; cc++) {
                            int nt = wn * 32 + nf * 8 + (lid & 3) * 2 + cc;
                            float v = acc[p][q][mf][nf][rh * 2 + cc] + b1s[nt];
                            v = (v < 0.0f) ? 0.1f * v : v;
                            s = fmaf(w2f[nt], v, s);
                        }
                    }
                    s += __shfl_xor_sync(0xFFFFFFFFu, s, 1);
                    s += __shfl_xor_sync(0xFFFFFFFFu, s, 2);
                    if ((lid & 3) == 0) {
                        int row = mf * 16 + rh * 8 + (lid >> 2);
                        part[wn * 128 + (p * 2 + q) * 32 + row] = s;
                    }
                }
            }
        }
    }
    __syncthreads();

    #pragma unroll
    for (int io = 0; io < 2; io++) {
        int v    = tid + io * 128;        // 0..255
        int chan = v >> 7;                // 0..1
        int idx  = v & 127;
        float s  = part[(chan * 2) * 128 + idx] + part[(chan * 2 + 1) * 128 + idx]
                 + b2f[chan];
        int pos = idx >> 5, row = idx & 31;
        int p = pos >> 1, q = pos & 1;
        int m = ptile * MT_CTA + row;
        int b = m >> 8, ty = (m >> 4) & 15, tx = m & 15;
        int o = ntile * 2 + chan;
        out[(((size_t)b * 128 + o) * 32 + 2 * ty + p) * 32 + 2 * tx + q] = s;
    }
}

// ----------------------------------------------------------------------------
extern "C" void kernel_launch(void* const* d_in, const int* in_sizes, int n_in,
                              void* d_out, int out_size) {
    const float* x  = (const float*)d_in[0];
    const float* w1 = (const float*)d_in[1];
    const float* b1 = (const float*)d_in[2];
    const float* w2 = (const float*)d_in[3];
    const float* b2 = (const float*)d_in[4];
    float* out = (float*)d_out;

    cudaFuncSetAttribute(wino_gemm, cudaFuncAttributeMaxDynamicSharedMemorySize,
                         SMEM_BYTES);

    wino_prep<<<IN_BLOCKS + W_BLOCKS, 256>>>(x, w1);
    wino_gemm<<<64 * 64, 128, SMEM_BYTES>>>(b1, w2, b2, out);
}